// round 16
// baseline (speedup 1.0000x reference)
#include <cuda_runtime.h>

// ---------------- problem constants ----------------
#define Bsz 512
#define Ssz 1024
#define Isz 64
#define Hsz 256
#define Gsz 768   // 3*H

// ---------------- recurrence partition ----------------
#define NI   32            // batch groups
#define MBLK 16            // batch rows per group
#define NJ   4             // hidden-column slices
#define NCTA (NI*NJ)       // 128 persistent CTAs

#define WSTRIDE 192        // row stride (floats) for Wh^T tile [256][192]
#define HSTRIDE 16         // row stride (floats) for h^T tile [256][16]
#define BUFSTR  66         // ull row stride of reduction buffer (pad vs bank conflicts)
// smem: Wh tile + h^T tile + reduction buffer buf[24][BUFSTR] ull
#define SMEM_GRU ((256*WSTRIDE + 256*HSTRIDE) * 4 + 24*BUFSTR*8)   // 225664 bytes

// ---------------- gate_x GEMM tiling ----------------
#define GX_MT 128
#define GX_NT 192
#define GX_SMEM ((64*128 + 64*192) * 4)              // 81920 bytes

// ---------------- static scratch (no allocations allowed) ----------------
__device__ float g_gatex[1ULL * Ssz * Bsz * Gsz];    // [S][B][G]  ~1.61 GB
__device__ float g_h[2][Bsz][Hsz];                   // double-buffered hidden state
__device__ int   g_cnt[NI][Ssz];                     // per-group per-step arrival counters

// ---------------- helpers ----------------
__device__ __forceinline__ unsigned long long pk2(float a, float b) {
    unsigned long long r;
    asm("mov.b64 %0, {%1, %2};" : "=l"(r) : "f"(a), "f"(b));
    return r;
}
__device__ __forceinline__ float2 u2f2(unsigned long long v) {
    float2 r;
    asm("mov.b64 {%0, %1}, %2;" : "=f"(r.x), "=f"(r.y) : "l"(v));
    return r;
}
__device__ __forceinline__ void fma2(unsigned long long& d,
                                     unsigned long long a, unsigned long long b) {
    asm("fma.rn.f32x2 %0, %1, %2, %0;" : "+l"(d) : "l"(a), "l"(b));
}
__device__ __forceinline__ void add2(unsigned long long& d, unsigned long long a) {
    asm("add.rn.f32x2 %0, %0, %1;" : "+l"(d) : "l"(a));
}
__device__ __forceinline__ float tanhA(float x) {
    float y;
    asm("tanh.approx.f32 %0, %1;" : "=f"(y) : "f"(x));
    return y;
}
__device__ __forceinline__ float sigA(float x) {
    return fmaf(tanhA(0.5f * x), 0.5f, 0.5f);
}
__device__ __forceinline__ float elem4(float4 v, int l) {
    return (l == 0) ? v.x : (l == 1) ? v.y : (l == 2) ? v.z : v.w;
}
__device__ __forceinline__ int ld_acq(const int* p) {
    int v;
    asm volatile("ld.acquire.gpu.global.b32 %0, [%1];" : "=r"(v) : "l"(p) : "memory");
    return v;
}
__device__ __forceinline__ void red_rel_add1(int* p) {
    asm volatile("red.release.gpu.global.add.s32 [%0], 1;" :: "l"(p) : "memory");
}
__device__ __forceinline__ float4 ldcg4(const float* p) {
    float4 v;
    asm volatile("ld.global.cg.v4.f32 {%0,%1,%2,%3}, [%4];"
                 : "=f"(v.x), "=f"(v.y), "=f"(v.z), "=f"(v.w) : "l"(p) : "memory");
    return v;
}
__device__ __forceinline__ void stcg4(float* p, float4 v) {
    asm volatile("st.global.cg.v4.f32 [%0], {%1,%2,%3,%4};"
                 :: "l"(p), "f"(v.x), "f"(v.y), "f"(v.z), "f"(v.w) : "memory");
}

// GEMM chunk: 16 k-iters, 16 m-rows (8 packed pairs) x 3 gates per thread
__device__ __forceinline__ void gemm16(const float* __restrict__ hsT,
                                       const float* __restrict__ wsT,
                                       int k0, int ncg3,
                                       unsigned long long acc[8][3]) {
#pragma unroll 4
    for (int k = k0; k < k0 + 16; k++) {
        const float* hr_ = &hsT[k * HSTRIDE];
        ulonglong2 ha = *(const ulonglong2*)(hr_ + 0);
        ulonglong2 hb = *(const ulonglong2*)(hr_ + 4);
        ulonglong2 hc_ = *(const ulonglong2*)(hr_ + 8);
        ulonglong2 hd = *(const ulonglong2*)(hr_ + 12);
        const float* wr_ = &wsT[k * WSTRIDE + ncg3];
        unsigned long long W0 = pk2(wr_[0], wr_[0]);
        unsigned long long W1 = pk2(wr_[1], wr_[1]);
        unsigned long long W2 = pk2(wr_[2], wr_[2]);
        fma2(acc[0][0], ha.x, W0); fma2(acc[0][1], ha.x, W1); fma2(acc[0][2], ha.x, W2);
        fma2(acc[1][0], ha.y, W0); fma2(acc[1][1], ha.y, W1); fma2(acc[1][2], ha.y, W2);
        fma2(acc[2][0], hb.x, W0); fma2(acc[2][1], hb.x, W1); fma2(acc[2][2], hb.x, W2);
        fma2(acc[3][0], hb.y, W0); fma2(acc[3][1], hb.y, W1); fma2(acc[3][2], hb.y, W2);
        fma2(acc[4][0], hc_.x, W0); fma2(acc[4][1], hc_.x, W1); fma2(acc[4][2], hc_.x, W2);
        fma2(acc[5][0], hc_.y, W0); fma2(acc[5][1], hc_.y, W1); fma2(acc[5][2], hc_.y, W2);
        fma2(acc[6][0], hd.x, W0); fma2(acc[6][1], hd.x, W1); fma2(acc[6][2], hd.x, W2);
        fma2(acc[7][0], hd.y, W0); fma2(acc[7][1], hd.y, W1); fma2(acc[7][2], hd.y, W2);
    }
}

// ---------------- no-op kernel: ncu window alignment (profiled slot = launch idx 3) ----------------
__global__ void k_nop() {}

// ---------------- kernel 0: per-replay state reset (counters) ----------------
__global__ void k_init() {
    int i = blockIdx.x * blockDim.x + threadIdx.x;
    if (i < NI * Ssz) ((int*)g_cnt)[i] = 0;
}

// ---------------- kernel 1: gate_x[s][b][g] = sum_i x[b][s][i] * Wx[g][i] ----------------
__global__ __launch_bounds__(256, 1)
void k_gatex(const float* __restrict__ x, const float* __restrict__ Wx) {
    extern __shared__ float sm[];
    float* xsT = sm;              // [64][128]
    float* wsT = sm + 64 * 128;   // [64][192]

    const int tid = threadIdx.x;
    const int r0  = (blockIdx.x >> 2) * GX_MT;
    const int g0  = (blockIdx.x & 3) * GX_NT;

    for (int t = tid; t < 128 * 16; t += 256) {
        int m = t >> 4, k4 = (t & 15) << 2;
        float4 v = *(const float4*)(x + (size_t)(r0 + m) * Isz + k4);
        xsT[(k4 + 0) * 128 + m] = v.x;
        xsT[(k4 + 1) * 128 + m] = v.y;
        xsT[(k4 + 2) * 128 + m] = v.z;
        xsT[(k4 + 3) * 128 + m] = v.w;
    }
    for (int t = tid; t < 192 * 16; t += 256) {
        int n = t >> 4, k4 = (t & 15) << 2;
        float4 v = *(const float4*)(Wx + (size_t)(g0 + n) * Isz + k4);
        wsT[(k4 + 0) * 192 + n] = v.x;
        wsT[(k4 + 1) * 192 + n] = v.y;
        wsT[(k4 + 2) * 192 + n] = v.z;
        wsT[(k4 + 3) * 192 + n] = v.w;
    }
    __syncthreads();

    const int mb = (tid >> 4) * 8;
    const int nb = (tid & 15) * 12;

    unsigned long long acc[8][6];
#pragma unroll
    for (int m = 0; m < 8; m++)
#pragma unroll
        for (int p = 0; p < 6; p++) acc[m][p] = 0ULL;

#pragma unroll 4
    for (int k = 0; k < 64; k++) {
        float4 xa = *(const float4*)&xsT[k * 128 + mb];
        float4 xb = *(const float4*)&xsT[k * 128 + mb + 4];
        ulonglong2 w0 = *(const ulonglong2*)&wsT[k * 192 + nb];
        ulonglong2 w1 = *(const ulonglong2*)&wsT[k * 192 + nb + 4];
        ulonglong2 w2 = *(const ulonglong2*)&wsT[k * 192 + nb + 8];
        unsigned long long wv[6] = {w0.x, w0.y, w1.x, w1.y, w2.x, w2.y};
        float xm[8] = {xa.x, xa.y, xa.z, xa.w, xb.x, xb.y, xb.z, xb.w};
#pragma unroll
        for (int m = 0; m < 8; m++) {
            unsigned long long xx = pk2(xm[m], xm[m]);
#pragma unroll
            for (int p = 0; p < 6; p++) fma2(acc[m][p], xx, wv[p]);
        }
    }

#pragma unroll
    for (int m = 0; m < 8; m++) {
        int r = r0 + mb + m;
        int b = r >> 10, s = r & 1023;
        float* op = g_gatex + ((size_t)s * Bsz + b) * Gsz + g0 + nb;
#pragma unroll
        for (int q = 0; q < 3; q++) {
            float2 a = u2f2(acc[m][2 * q]);
            float2 c = u2f2(acc[m][2 * q + 1]);
            *(float4*)(op + 4 * q) = make_float4(a.x, a.y, c.x, c.y);
        }
    }
}

// ---------------- kernel 2: persistent GRU recurrence (phase-split exchange hiding) ----------------
// CTA (gi, j): batch rows [gi*16,+16), hidden cols [j*64,+64). 256 threads.
// GEMM thread (ks=tid>>6, ncg=tid&63): 16 m x 3 gates over a 64-k slice, split:
//   phase 1 (16 k, own rows [jc+ks*16,+16), current in smem)  BEFORE the peer wait
//   phase 2 (48 k, the 3 peer blocks)                         AFTER the wait
// Epilogue thread (c4=tid>>4, mrow=tid&15): cols jc+c4*4..+3, row mrow; writes
// own h-slice to hsT (smem residency) and publishes via st.global.cg.v4.
__global__ __launch_bounds__(256, 1)
void k_gru(const float* __restrict__ Wh, const float* __restrict__ bias) {
    extern __shared__ float sm[];
    float* wsT = sm;                                        // [256][WSTRIDE]
    float* hsT = sm + 256 * WSTRIDE;                        // [256][HSTRIDE]
    unsigned long long* buf =
        (unsigned long long*)(sm + 256 * WSTRIDE + 256 * HSTRIDE);  // [24][BUFSTR]

    const int tid = threadIdx.x;
    const int gi  = blockIdx.x >> 2;
    const int j   = blockIdx.x & 3;
    const int b0  = gi * MBLK;
    const int jc  = j * 64;
    // GEMM mapping
    const int ks   = tid >> 6;           // k-subslice 0..3 (warp-uniform)
    const int ncg  = tid & 63;           // gemm column 0..63
    const int ncg3 = ncg * 3;
    // epilogue mapping
    const int c4   = tid >> 4;           // col-quad 0..15
    const int mrow = tid & 15;           // batch row 0..15
    const int ec0  = jc + c4 * 4;        // global col base
    const int pair = mrow >> 1, sel = mrow & 1;

    // load Wh slice, transposed + gate-interleaved (K=256: 192 rows x 64 float4-groups)
    for (int t = tid; t < 192 * 64; t += 256) {
        int row = t >> 6, k4 = (t & 63) << 2;
        int g = row / 64, hc = row % 64;
        float4 v = *(const float4*)(Wh + (size_t)(g * Hsz + jc + hc) * Hsz + k4);
        int n = hc * 3 + g;
        wsT[(k4 + 0) * WSTRIDE + n] = v.x;
        wsT[(k4 + 1) * WSTRIDE + n] = v.y;
        wsT[(k4 + 2) * WSTRIDE + n] = v.z;
        wsT[(k4 + 3) * WSTRIDE + n] = v.w;
    }
    // zero h tile (h0 = 0; own slice maintained by epilogue from here on)
    for (int t = tid; t < 256 * HSTRIDE; t += 256) hsT[t] = 0.0f;

    const float4 br4 = *(const float4*)(bias + 0 * Hsz + ec0);
    const float4 bz4 = *(const float4*)(bias + 1 * Hsz + ec0);
    const float4 bh4 = *(const float4*)(bias + 2 * Hsz + ec0);

    float hprev[4];                      // own h (row mrow, cols ec0..+3)
#pragma unroll
    for (int i = 0; i < 4; i++) hprev[i] = 0.0f;

    __syncthreads();

    int* cnt = &g_cnt[gi][0];
    const int jq = j * 16;               // own kq range [jq, jq+16)

    for (int s = 0; s < Ssz; s++) {
        const float* hprevg = &g_h[s & 1][0][0];
        float*       hnextg = &g_h[(s + 1) & 1][0][0];

        // prefetch this step's input gates (epilogue cols; overlaps phase-1 + wait)
        const float* gxb = g_gatex + ((size_t)s * Bsz + b0 + mrow) * Gsz + ec0;
        float4 gr4 = ldcg4(gxb + 0);
        float4 gz4 = ldcg4(gxb + 256);
        float4 gh4 = ldcg4(gxb + 512);

        unsigned long long acc[8][3];
#pragma unroll
        for (int p = 0; p < 8; p++)
#pragma unroll
            for (int q = 0; q < 3; q++) acc[p][q] = 0ULL;

        // ---- phase 1: own rows (already in smem from previous epilogue) ----
        gemm16(hsT, wsT, jc + ks * 16, ncg3, acc);

        // ---- wait for peer slices, pull them into smem ----
        if (s > 0) {
            while (ld_acq(&cnt[s - 1]) < NJ) { }
#pragma unroll
            for (int it = 0; it < 3; it++) {
                int idx = tid + it * 256;
                int m = idx & 15, kq = idx >> 4;     // kq' in [0,48)
                kq += (kq >= jq) ? 16 : 0;           // skip own 16 kq-groups
                float4 v = ldcg4(hprevg + (size_t)(b0 + m) * Hsz + kq * 4);
                hsT[(kq * 4 + 0) * HSTRIDE + m] = v.x;
                hsT[(kq * 4 + 1) * HSTRIDE + m] = v.y;
                hsT[(kq * 4 + 2) * HSTRIDE + m] = v.z;
                hsT[(kq * 4 + 3) * HSTRIDE + m] = v.w;
            }
        }
        __syncthreads();

        // ---- phase 2: the 3 peer blocks ----
#pragma unroll
        for (int jb = 0; jb < 4; jb++)
            if (jb != j) gemm16(hsT, wsT, jb * 64 + ks * 16, ncg3, acc);

        // ---- k-split reduction: 4 serial RMW rounds into buf ----
        if (ks == 0) {
#pragma unroll
            for (int p = 0; p < 8; p++)
#pragma unroll
                for (int q = 0; q < 3; q++)
                    buf[(p * 3 + q) * BUFSTR + ncg] = acc[p][q];
        }
        __syncthreads();
#pragma unroll
        for (int r = 1; r < 4; r++) {
            if (ks == r) {
#pragma unroll
                for (int p = 0; p < 8; p++)
#pragma unroll
                    for (int q = 0; q < 3; q++) {
                        add2(acc[p][q], buf[(p * 3 + q) * BUFSTR + ncg]);
                        buf[(p * 3 + q) * BUFSTR + ncg] = acc[p][q];
                    }
            }
            __syncthreads();
        }

        // ---- epilogue: thread (c4, mrow) -> cols ec0..+3, row mrow ----
        float hv[3][4];
#pragma unroll
        for (int q = 0; q < 3; q++)
#pragma unroll
            for (int i = 0; i < 4; i++) {
                float2 f = u2f2(buf[(pair * 3 + q) * BUFSTR + c4 * 4 + i]);
                hv[q][i] = sel ? f.y : f.x;
            }

        float4 hy4;
        float* hyp = (float*)&hy4;
#pragma unroll
        for (int i = 0; i < 4; i++) {
            float rg = sigA(elem4(gr4, i) + hv[0][i] + elem4(br4, i));
            float zg = sigA(elem4(gz4, i) + hv[1][i] + elem4(bz4, i));
            float ng = tanhA(elem4(gh4, i) + rg * hv[2][i] + elem4(bh4, i));
            float hy = ng + zg * (hprev[i] - ng);
            hprev[i] = hy;
            hyp[i] = hy;
            hsT[(ec0 + i) * HSTRIDE + mrow] = hy;    // own-slice smem residency
        }
        stcg4(hnextg + (size_t)(b0 + mrow) * Hsz + ec0, hy4);

        __syncthreads();                          // epilogue smem/global writes done
        if (tid == 0) red_rel_add1(&cnt[s]);      // gpu-scope release publishes them
    }
}

// ---------------- kernel 3: logits = h_T @ fc_w^T + fc_b ----------------
__global__ void k_fc(const float* __restrict__ fc_w, const float* __restrict__ fc_b,
                     float* __restrict__ out) {
    int b = blockIdx.x;
    int c = threadIdx.x >> 5;
    int lane = threadIdx.x & 31;
    const float* h = &g_h[0][b][0];   // final h lives in buffer 0 (1024 is even)
    float sum = 0.0f;
#pragma unroll
    for (int k = lane; k < Hsz; k += 32)
        sum += h[k] * fc_w[c * Hsz + k];
#pragma unroll
    for (int o = 16; o > 0; o >>= 1)
        sum += __shfl_xor_sync(0xffffffffu, sum, o);
    if (lane == 0)
        out[b * 10 + c] = sum + fc_b[c];
}

// ---------------- launch ----------------
extern "C" void kernel_launch(void* const* d_in, const int* in_sizes, int n_in,
                              void* d_out, int out_size) {
    // Map inputs by UNIQUE element counts (robust to metadata ordering).
    const float *x = 0, *Wx = 0, *Wh = 0, *bias = 0, *fc_w = 0, *fc_b = 0;
    for (int i = 0; i < n_in; i++) {
        switch (in_sizes[i]) {
            case Bsz * Ssz * Isz: x    = (const float*)d_in[i]; break;
            case Gsz * Isz:       Wx   = (const float*)d_in[i]; break;
            case Gsz * Hsz:       Wh   = (const float*)d_in[i]; break;
            case Gsz:             bias = (const float*)d_in[i]; break;
            case 10 * Hsz:        fc_w = (const float*)d_in[i]; break;
            case 10:              fc_b = (const float*)d_in[i]; break;
            default: break;
        }
    }
    if (!x || !Wx || !Wh || !bias || !fc_w || !fc_b) {
        x    = (const float*)d_in[0];
        Wx   = (const float*)d_in[1];
        Wh   = (const float*)d_in[2];
        bias = (const float*)d_in[3];
        fc_w = (const float*)d_in[4];
        fc_b = (const float*)d_in[5];
    }
    float* out = (float*)d_out;

    cudaFuncSetAttribute(k_gatex, cudaFuncAttributeMaxDynamicSharedMemorySize, GX_SMEM);
    cudaFuncSetAttribute(k_gru,   cudaFuncAttributeMaxDynamicSharedMemorySize, SMEM_GRU);

    // ncu's profiled slot = launch idx 3 -> keep k_gru there
    k_nop<<<1, 32>>>();
    k_init<<<128, 256>>>();
    k_gatex<<<16384, 256, GX_SMEM>>>(x, Wx);
    k_gru<<<NCTA, 256, SMEM_GRU>>>(Wh, bias);
    k_fc<<<512, 320>>>(fc_w, fc_b, out);
}